// round 15
// baseline (speedup 1.0000x reference)
#include <cuda_runtime.h>

#define DD 64
#define HH 512
#define WW 512
#define W4 (WW / 4)
#define THRESH 0.5f

#define WT 8                 // float4 columns per block
#define TH 16                // output rows per block
#define YROWS (TH + 8)       // 24 W-maxed rows needed per plane
#define NTRIPS (DD + 8)      // 72 (multiple of 9)

__device__ __forceinline__ float4 vmax4(float4 a, float4 b) {
    return make_float4(fmaxf(a.x, b.x), fmaxf(a.y, b.y),
                       fmaxf(a.z, b.z), fmaxf(a.w, b.w));
}

// ---------------------------------------------------------------------------
// Fully fused: threshold-deferred 9x9x9 max-pool + strict-local-max gate.
// No intermediate volume. Per D-trip: block computes 24 W-maxed rows into
// smem (double buffer, one sync), each thread H-maxes 9 values -> whmax,
// flags (whmax == raw center, L1 hit) into the sign of s, and runs the
// van Herk D-window pipeline (ring of unsigned whmax + running prefix P,
// in-place ring suffix at trip%9==8; emit m = max(S, P)). Gate:
// out = m if (m > 0.5 && s_center == m) else 0. Clamp-to-edge everywhere
// (exact for max-pool: clamped duplicates are already inside the window).
// grid (W4/WT, HH/TH) = (16, 32), block 128.
// ---------------------------------------------------------------------------
__global__ void __launch_bounds__(128) k_fused(const float4* __restrict__ in,
                                               float4* __restrict__ out) {
    __shared__ float4 ybuf[2][YROWS][WT + 1];   // +1 pad

    const int t   = threadIdx.x;
    const int w4l = t & (WT - 1);
    const int hl  = t >> 3;                     // 0..15
    const int w0  = blockIdx.x * WT;
    const int h0  = blockIdx.y * TH;
    const int w4g = w0 + w4l;
    const int hg  = h0 + hl;
    const size_t slice = (size_t)HH * W4;

    // y-slot assignments: slot A = (row hl, w4l); slot B = (row hl+16, w4l)
    // active only for t < 64  (24*8 - 128 = 64 extra slots)
    const bool hasB = (t < (YROWS * WT - 128));
    const int  gyA  = min(max(h0 + hl - 4, 0), HH - 1);
    const int  gyB  = min(max(h0 + hl + 12, 0), HH - 1);   // (hl+16)-4
    const int  xl   = max(w4g - 1, 0);
    const int  xr   = min(w4g + 1, W4 - 1);

    const float4 z4 = make_float4(0.f, 0.f, 0.f, 0.f);
    float4 ring[9];
    float4 P = z4;
    float4 c0 = z4, c1 = z4, c2 = z4, c3 = z4;  // signed whmax delay (4 planes)

#pragma unroll 9
    for (int di = 0; di < NTRIPS; di++) {
        const int pc = min(max(di - 4, 0), DD - 1);        // cursor plane
        const float4* plane = in + (size_t)pc * slice;
        const int b = di & 1;

        // ---- W-max rows into smem (slot A, then slot B) ----
        {
            const float4* row = plane + (size_t)gyA * W4;
            const float4 L = row[xl], M = row[w4g], R = row[xr];
            float c  = fmaxf(fmaxf(fmaxf(L.w, M.x), fmaxf(M.y, M.z)),
                             fmaxf(M.w, R.x));
            float u1 = fmaxf(L.y, L.z);
            float u2 = fmaxf(R.y, R.z);
            float4 y;
            y.x = fmaxf(fmaxf(c, L.x), u1);
            y.y = fmaxf(fmaxf(c, R.y), u1);
            y.z = fmaxf(fmaxf(c, L.z), u2);
            y.w = fmaxf(fmaxf(c, R.w), u2);
            ybuf[b][hl][w4l] = y;
        }
        if (hasB) {
            const float4* row = plane + (size_t)gyB * W4;
            const float4 L = row[xl], M = row[w4g], R = row[xr];
            float c  = fmaxf(fmaxf(fmaxf(L.w, M.x), fmaxf(M.y, M.z)),
                             fmaxf(M.w, R.x));
            float u1 = fmaxf(L.y, L.z);
            float u2 = fmaxf(R.y, R.z);
            float4 y;
            y.x = fmaxf(fmaxf(c, L.x), u1);
            y.y = fmaxf(fmaxf(c, R.y), u1);
            y.z = fmaxf(fmaxf(c, L.z), u2);
            y.w = fmaxf(fmaxf(c, R.w), u2);
            ybuf[b][hl + 16][w4l] = y;
        }
        __syncthreads();

        // ---- H-max over 9 smem rows -> whmax at (hg, w4g, pc) ----
        float4 m9 = ybuf[b][hl][w4l];
#pragma unroll
        for (int i = 1; i < 9; i++) m9 = vmax4(m9, ybuf[b][hl + i][w4l]);

        // raw center (L1 hit: loaded as M for row hg this trip)
        const float4 rawc = plane[(size_t)hg * W4 + w4g];
        float4 s;                       // +whmax if center is WH-max, else -
        s.x = (m9.x == rawc.x) ? m9.x : -m9.x;
        s.y = (m9.y == rawc.y) ? m9.y : -m9.y;
        s.z = (m9.z == rawc.z) ? m9.z : -m9.z;
        s.w = (m9.w == rawc.w) ? m9.w : -m9.w;

        // ---- van Herk D pipeline (ring holds unsigned whmax) ----
        ring[di % 9] = m9;
        P = (di % 9 == 0) ? m9 : vmax4(P, m9);

        if (di % 9 == 8) {              // segment end: in-place suffix pass
#pragma unroll
            for (int i = 7; i >= 0; i--) ring[i] = vmax4(ring[i], ring[i + 1]);
        }

        if (di >= 8) {
            const int o = di - 8;       // output plane, 0..63
            float4 m = vmax4(ring[(di - 8) % 9], P);
            const float4 cv = c3;       // signed whmax at center plane o
            float4 ov;
            ov.x = (m.x > THRESH && cv.x == m.x) ? m.x : 0.f;
            ov.y = (m.y > THRESH && cv.y == m.y) ? m.y : 0.f;
            ov.z = (m.z > THRESH && cv.z == m.z) ? m.z : 0.f;
            ov.w = (m.w > THRESH && cv.w == m.w) ? m.w : 0.f;
            out[(size_t)o * slice + (size_t)hg * W4 + w4g] = ov;
        }

        c3 = c2; c2 = c1; c1 = c0; c0 = s;   // 4-plane delay
    }
}

extern "C" void kernel_launch(void* const* d_in, const int* in_sizes, int n_in,
                              void* d_out, int out_size) {
    const float4* in  = (const float4*)d_in[0];
    float4*       out = (float4*)d_out;

    dim3 g(W4 / WT, HH / TH);            // (16, 32) = 512 blocks
    k_fused<<<g, 128>>>(in, out);
}

// round 16
// speedup vs baseline: 1.1539x; 1.1539x over previous
#include <cuda_runtime.h>

#define DD 64
#define HH 512
#define WW 512
#define W4 (WW / 4)
#define THRESH 0.5f

#define WT 8                 // float4 columns per block
#define TH 16                // output rows per block
#define YROWS (TH + 8)       // 24 W-maxed rows per plane
#define DSEG 16              // output planes per block -> 24 trips

__device__ __forceinline__ float4 vmax4(float4 a, float4 b) {
    return make_float4(fmaxf(a.x, b.x), fmaxf(a.y, b.y),
                       fmaxf(a.z, b.z), fmaxf(a.w, b.w));
}

// ---------------------------------------------------------------------------
// Fully fused 9x9x9 threshold+maxpool+strict-local-max, D-split for grid
// size. Per trip (cursor plane pc): block W-maxes YROWS halo rows into smem
// (double buffer, one sync), each thread H-maxes 9 rows -> whmax, flags
// (whmax == raw center, L1 hit) into sign of s, runs van Herk D pipeline
// (ring of unsigned whmax + prefix P, in-place suffix at trip%9==8), and a
// 4-deep signed delay chain provides the center plane at emit. Gate:
// out = m if (m > 0.5 && s_center == m) else 0. Clamp-to-edge everywhere
// (exact). The delay chain self-fills during the 8 warmup trips: c3 at the
// first emit (di=8) is s of plane d0. grid (16, 32, 4) = 2048, block 128.
// ---------------------------------------------------------------------------
__global__ void __launch_bounds__(128) k_fused(const float4* __restrict__ in,
                                               float4* __restrict__ out) {
    __shared__ float4 ybuf[2][YROWS][WT + 1];   // +1 pad vs bank conflicts

    const int t   = threadIdx.x;
    const int w4l = t & (WT - 1);
    const int hl  = t >> 3;                     // 0..15
    const int w4g = blockIdx.x * WT + w4l;
    const int h0  = blockIdx.y * TH;
    const int hg  = h0 + hl;
    const int d0  = blockIdx.z * DSEG;
    const size_t slice = (size_t)HH * W4;

    // smem slots: A = row hl, B = row hl+16 (first 64 threads only)
    const bool hasB = (t < (YROWS * WT - 128));          // t < 64
    const int  gyA  = min(max(h0 + hl - 4, 0), HH - 1);
    const int  gyB  = min(max(h0 + hl + 12, 0), HH - 1); // (hl+16)-4
    const int  xl   = max(w4g - 1, 0);
    const int  xr   = min(w4g + 1, W4 - 1);

    const float4 z4 = make_float4(0.f, 0.f, 0.f, 0.f);
    float4 ring[9];
    float4 P = z4;
    float4 c0 = z4, c1 = z4, c2 = z4, c3 = z4;  // signed whmax 4-plane delay

#pragma unroll
    for (int di = 0; di < DSEG + 8; di++) {     // 24 trips, fully unrolled
        const int pc = min(max(d0 + di - 4, 0), DD - 1);   // cursor plane
        const float4* plane = in + (size_t)pc * slice;
        const int b = di & 1;

        // ---- W-max halo rows into smem ----
        {
            const float4* row = plane + (size_t)gyA * W4;
            const float4 L = row[xl], M = row[w4g], R = row[xr];
            float c  = fmaxf(fmaxf(fmaxf(L.w, M.x), fmaxf(M.y, M.z)),
                             fmaxf(M.w, R.x));
            float u1 = fmaxf(L.y, L.z);
            float u2 = fmaxf(R.y, R.z);
            float4 y;
            y.x = fmaxf(fmaxf(c, L.x), u1);
            y.y = fmaxf(fmaxf(c, R.y), u1);
            y.z = fmaxf(fmaxf(c, L.z), u2);
            y.w = fmaxf(fmaxf(c, R.w), u2);
            ybuf[b][hl][w4l] = y;
        }
        if (hasB) {
            const float4* row = plane + (size_t)gyB * W4;
            const float4 L = row[xl], M = row[w4g], R = row[xr];
            float c  = fmaxf(fmaxf(fmaxf(L.w, M.x), fmaxf(M.y, M.z)),
                             fmaxf(M.w, R.x));
            float u1 = fmaxf(L.y, L.z);
            float u2 = fmaxf(R.y, R.z);
            float4 y;
            y.x = fmaxf(fmaxf(c, L.x), u1);
            y.y = fmaxf(fmaxf(c, R.y), u1);
            y.z = fmaxf(fmaxf(c, L.z), u2);
            y.w = fmaxf(fmaxf(c, R.w), u2);
            ybuf[b][hl + 16][w4l] = y;
        }
        __syncthreads();

        // ---- H-max over 9 smem rows -> whmax at (hg, w4g, pc) ----
        float4 m9 = ybuf[b][hl][w4l];
#pragma unroll
        for (int i = 1; i < 9; i++) m9 = vmax4(m9, ybuf[b][hl + i][w4l]);

        // raw center (L1 hit: this row was loaded as M this trip)
        const float4 rawc = plane[(size_t)hg * W4 + w4g];
        float4 s;                       // +whmax if center is WH-max, else -
        s.x = (m9.x == rawc.x) ? m9.x : -m9.x;
        s.y = (m9.y == rawc.y) ? m9.y : -m9.y;
        s.z = (m9.z == rawc.z) ? m9.z : -m9.z;
        s.w = (m9.w == rawc.w) ? m9.w : -m9.w;

        // ---- van Herk D pipeline ----
        ring[di % 9] = m9;
        P = (di % 9 == 0) ? m9 : vmax4(P, m9);

        if (di % 9 == 8) {              // di = 8, 17: in-place suffix pass
#pragma unroll
            for (int i = 7; i >= 0; i--) ring[i] = vmax4(ring[i], ring[i + 1]);
        }

        if (di >= 8) {
            const int o = d0 + di - 8;  // output plane in [d0, d0+DSEG)
            float4 m = vmax4(ring[(di - 8) % 9], P);
            const float4 cv = c3;       // signed whmax at center plane o
            float4 ov;
            ov.x = (m.x > THRESH && cv.x == m.x) ? m.x : 0.f;
            ov.y = (m.y > THRESH && cv.y == m.y) ? m.y : 0.f;
            ov.z = (m.z > THRESH && cv.z == m.z) ? m.z : 0.f;
            ov.w = (m.w > THRESH && cv.w == m.w) ? m.w : 0.f;
            out[(size_t)o * slice + (size_t)hg * W4 + w4g] = ov;
        }

        c3 = c2; c2 = c1; c1 = c0; c0 = s;   // 4-plane delay (renamed)
    }
}

extern "C" void kernel_launch(void* const* d_in, const int* in_sizes, int n_in,
                              void* d_out, int out_size) {
    const float4* in  = (const float4*)d_in[0];
    float4*       out = (float4*)d_out;

    dim3 g(W4 / WT, HH / TH, DD / DSEG);  // (16, 32, 4) = 2048 blocks
    k_fused<<<g, 128>>>(in, out);
}

// round 17
// speedup vs baseline: 1.7797x; 1.5423x over previous
#include <cuda_runtime.h>

#define DD 64
#define HH 512
#define WW 512
#define W4 (WW / 4)
#define THRESH 0.5f

// 64 MB scratch (device global, allocation-free rule). Convention:
//   stored value = +whmax  if raw center == 9x9 WH-window max (flag set)
//                = -whmax  otherwise.
__device__ float4 g_tmp[(size_t)DD * HH * W4];

#define TH1 16   // H rows per k1 block -> 24 trips; 32 y-blocks cover 512
#define DSEG 16  // D outputs per thread in k2 -> 24 trips

__device__ __forceinline__ float4 vmax4(float4 a, float4 b) {
    return make_float4(fmaxf(a.x, b.x), fmaxf(a.y, b.y),
                       fmaxf(a.z, b.z), fmaxf(a.w, b.w));
}
__device__ __forceinline__ float4 vabs4(float4 a) {
    return make_float4(fabsf(a.x), fabsf(a.y), fabsf(a.z), fabsf(a.w));
}

// ---------------------------------------------------------------------------
// k1: block = full W row (128 float4 threads). Per trip: ONE coalesced
// global load per thread into a double-buffered smem row (132 slots; edge
// threads duplicate the clamped ends), L/R neighbors come from smem. 9-tap
// W max (tree) + 9-tap H max via van Herk (in-place ring suffix at
// trip%9==8, running prefix P). Clamp-to-edge everywhere (exact for
// max-pool). Flag (whmax == raw center, re-read at emit, L1 hit) packed as
// the sign of the stored value. Double buffer => one sync per trip is safe
// (a warp one trip ahead writes the other buffer). grid (1, 32, 64).
// ---------------------------------------------------------------------------
__global__ void __launch_bounds__(128) k_wh(const float4* __restrict__ in) {
    __shared__ float4 srow[2][W4 + 4];          // slot i+1 = column i, +pad

    const int t  = threadIdx.x;                 // 0..127 (= W4-1)
    const int h0 = blockIdx.y * TH1;
    const int d  = blockIdx.z;
    const float4* base = in    + (size_t)d * HH * W4;
    float4*       tmpb = g_tmp + (size_t)d * HH * W4;

    float4 ring[9];
    float4 P;

#pragma unroll
    for (int hh = 0; hh < TH1 + 8; hh++) {      // 24 trips, fully unrolled
        const int hc = min(max(h0 - 4 + hh, 0), HH - 1);
        const int b  = hh & 1;

        const float4 M = base[(size_t)hc * W4 + t];   // single coalesced load
        srow[b][t + 1] = M;
        if (t == 0)      srow[b][0]      = M;   // clamp-to-edge duplicate
        if (t == W4 - 1) srow[b][W4 + 1] = M;
        __syncthreads();

        const float4 L = srow[b][t];            // row[t-1] (clamped)
        const float4 R = srow[b][t + 2];        // row[t+1] (clamped)

        // 9-tap W max: a0..a11 = L.xyzw M.xyzw R.xyzw, out_i = max(a[i..i+8])
        float c  = fmaxf(fmaxf(fmaxf(L.w, M.x), fmaxf(M.y, M.z)),
                         fmaxf(M.w, R.x));      // max(a3..a8)
        float u1 = fmaxf(L.y, L.z);
        float u2 = fmaxf(R.y, R.z);
        float4 y;
        y.x = fmaxf(fmaxf(c, L.x), u1);
        y.y = fmaxf(fmaxf(c, R.y), u1);
        y.z = fmaxf(fmaxf(c, L.z), u2);
        y.w = fmaxf(fmaxf(c, R.w), u2);

        ring[hh % 9] = y;                       // static index (full unroll)
        P = (hh % 9 == 0) ? y : vmax4(P, y);    // prefix within segment

        if (hh % 9 == 8) {                      // segment end: in-place suffix
#pragma unroll
            for (int i = 7; i >= 0; i--) ring[i] = vmax4(ring[i], ring[i + 1]);
        }

        if (hh >= 8) {                          // output row always valid
            const int ho = h0 + hh - 8;
            float4 m = vmax4(ring[(hh - 8) % 9], P);
            const float4 cen = base[(size_t)ho * W4 + t];   // L1 hit
            float4 o;               // +m if center is WH-window max, else -m
            o.x = (m.x == cen.x) ? m.x : -m.x;
            o.y = (m.y == cen.y) ? m.y : -m.y;
            o.z = (m.z == cen.z) ? m.z : -m.z;
            o.w = (m.w == cen.w) ? m.w : -m.w;
            tmpb[(size_t)ho * W4 + t] = o;
        }
    }
}

// ---------------------------------------------------------------------------
// k2 (R14-exact): 9-tap D max over |tmp| via van Herk, clamp-to-edge D
// padding, unconditional loads. Gate: out = m if (m > 0.5 && cv == m),
// cv = signed tmp at center plane (re-read, L1 hit). grid (512, 4).
// ---------------------------------------------------------------------------
__global__ void __launch_bounds__(128) k_d(float4* __restrict__ out) {
    const size_t col   = (size_t)blockIdx.x * 128 + threadIdx.x;
    const int    d0    = blockIdx.y * DSEG;
    const size_t slice = (size_t)HH * W4;

    float4 ring[9];
    float4 P;

#pragma unroll
    for (int di = 0; di < DSEG + 8; di++) {     // 24 trips, fully unrolled
        const int pc = min(max(d0 + di - 4, 0), DD - 1);
        const float4 a = vabs4(g_tmp[(size_t)pc * slice + col]);

        ring[di % 9] = a;
        P = (di % 9 == 0) ? a : vmax4(P, a);

        if (di % 9 == 8) {                      // di = 8, 17
#pragma unroll
            for (int i = 7; i >= 0; i--) ring[i] = vmax4(ring[i], ring[i + 1]);
        }

        if (di >= 8) {
            const int o = d0 + di - 8;
            float4 m = vmax4(ring[(di - 8) % 9], P);
            const float4 cv = g_tmp[(size_t)o * slice + col];   // L1 hit
            float4 ov;
            ov.x = (m.x > THRESH && cv.x == m.x) ? m.x : 0.f;
            ov.y = (m.y > THRESH && cv.y == m.y) ? m.y : 0.f;
            ov.z = (m.z > THRESH && cv.z == m.z) ? m.z : 0.f;
            ov.w = (m.w > THRESH && cv.w == m.w) ? m.w : 0.f;
            out[(size_t)o * slice + col] = ov;
        }
    }
}

extern "C" void kernel_launch(void* const* d_in, const int* in_sizes, int n_in,
                              void* d_out, int out_size) {
    const float4* in  = (const float4*)d_in[0];
    float4*       out = (float4*)d_out;

    dim3 g1(1, HH / TH1, DD);            // (1, 32, 64) = 2048 blocks
    k_wh<<<g1, 128>>>(in);

    dim3 g2((HH * W4) / 128, DD / DSEG); // (512, 4) = 2048 blocks
    k_d<<<g2, 128>>>(out);
}